// round 1
// baseline (speedup 1.0000x reference)
#include <cuda_runtime.h>
#include <math.h>

#define B  2
#define S  2048
#define IN 64
#define HID 512
#define NH 8
#define HD 64
#define RR 64
#define TK 16
#define BS (B*S)           // 4096
#define NQ (B*NH*S)        // 32768

// ---------------- scratch buffers (static device globals; no allocation) ----
__device__ float g_h[BS*HID];     // conv output (B,S,512)
__device__ float g_Q[NQ*HD];      // (B,NH,S,HD)
__device__ float g_K[NQ*HD];
__device__ float g_V[NQ*HD];
__device__ float g_Kp[NQ*RR];
__device__ float g_Vp[NQ*RR];
__device__ float g_attn[BS*HID];  // (B,S,512): local then combined
__device__ float g_res[BS*HID];   // pre-LN residual

// ============================================================== conv =======
template<int KSZ, int ROFF>
__device__ __forceinline__ void conv_accum(const float (*xs)[64],
                                           const float* __restrict__ w,
                                           float bias, float acc[16]) {
    #pragma unroll
    for (int p = 0; p < 16; p++) acc[p] = bias;
    for (int ic = 0; ic < 64; ic++) {
        float xc[15 + KSZ];
        #pragma unroll
        for (int r = 0; r < 15 + KSZ; r++) xc[r] = xs[ROFF + r][ic];
        #pragma unroll
        for (int t = 0; t < KSZ; t++) {
            float wv = w[ic*KSZ + t];
            #pragma unroll
            for (int p = 0; p < 16; p++) acc[p] += xc[p + t] * wv;
        }
    }
}

__global__ void conv_kernel(const float* __restrict__ x,
                            const float* __restrict__ w1, const float* __restrict__ b1,
                            const float* __restrict__ w2, const float* __restrict__ b2,
                            const float* __restrict__ w3, const float* __restrict__ b3) {
    __shared__ float xs[22][64];          // rows s0-3 .. s0+18
    int blk = blockIdx.x;                 // 0..255
    int b   = blk / (S/16);
    int s0  = (blk % (S/16)) * 16;
    for (int e = threadIdx.x; e < 22*64; e += 512) {
        int row = e >> 6, ic = e & 63;
        int s = s0 - 3 + row;
        xs[row][ic] = (s >= 0 && s < S) ? x[(b*S + s)*64 + ic] : 0.f;
    }
    __syncthreads();

    int oc = threadIdx.x;                 // 0..511
    float acc[16];
    if (oc < 171) {
        conv_accum<3,2>(xs, w1 + oc*64*3, b1[oc], acc);
    } else if (oc < 342) {
        int o = oc - 171;
        conv_accum<5,1>(xs, w2 + o*64*5, b2[o], acc);
    } else {
        int o = oc - 342;
        conv_accum<7,0>(xs, w3 + o*64*7, b3[o], acc);
    }
    #pragma unroll
    for (int p = 0; p < 16; p++)
        g_h[(b*S + s0 + p)*HID + oc] = fmaxf(acc[p], 0.f);
}

// ============================================== QKV projection GEMM ========
// out = h(4096x512) @ W^T(512x512) + bias, stored head-major (B,NH,S,HD)
__global__ void qkv_kernel(const float* __restrict__ Wq, const float* __restrict__ bq,
                           const float* __restrict__ Wk, const float* __restrict__ bk,
                           const float* __restrict__ Wv, const float* __restrict__ bv) {
    __shared__ float As[16][64];
    __shared__ float Bsm[16][64];
    int m0 = blockIdx.x * 64;
    int by = blockIdx.y;                  // 0..23
    const float *W, *bias; float* dst;
    if (by < 8)       { W = Wq; bias = bq; dst = g_Q; }
    else if (by < 16) { W = Wk; bias = bk; dst = g_K; }
    else              { W = Wv; bias = bv; dst = g_V; }
    int n0 = (by & 7) * 64;

    int tid = threadIdx.x;
    int tx = tid & 15, ty = tid >> 4;
    float acc[4][4] = {};

    for (int k0 = 0; k0 < 512; k0 += 16) {
        #pragma unroll
        for (int u = 0; u < 4; u++) {
            int e = tid + u*256;
            int row = e >> 4, col = e & 15;
            As[col][row]  = g_h[(m0+row)*HID + k0 + col];
            Bsm[col][row] = W[(n0+row)*HID + k0 + col];
        }
        __syncthreads();
        #pragma unroll
        for (int kk = 0; kk < 16; kk++) {
            float a[4], bb[4];
            #pragma unroll
            for (int i = 0; i < 4; i++) a[i]  = As[kk][ty*4 + i];
            #pragma unroll
            for (int j = 0; j < 4; j++) bb[j] = Bsm[kk][tx*4 + j];
            #pragma unroll
            for (int i = 0; i < 4; i++)
                #pragma unroll
                for (int j = 0; j < 4; j++) acc[i][j] += a[i]*bb[j];
        }
        __syncthreads();
    }
    #pragma unroll
    for (int i = 0; i < 4; i++) {
        int m = m0 + ty*4 + i;
        int b = m >> 11, s = m & 2047;
        #pragma unroll
        for (int j = 0; j < 4; j++) {
            int n = n0 + tx*4 + j;
            int head = n >> 6, d = n & 63;
            dst[((b*NH + head)*S + s)*HD + d] = acc[i][j] + bias[n];
        }
    }
}

// ============================================== Kp / Vp projections ========
__global__ void kpvp_kernel(const float* __restrict__ Wkp, const float* __restrict__ bkp,
                            const float* __restrict__ Wvp, const float* __restrict__ bvp) {
    __shared__ float kr[4][64], vr[4][64];
    int sub = threadIdx.x >> 6;
    int r   = threadIdx.x & 63;
    int pos = blockIdx.x*4 + sub;         // < 32768
    kr[sub][r] = g_K[pos*64 + r];
    vr[sub][r] = g_V[pos*64 + r];
    __syncthreads();
    float aK = bkp[r], aV = bvp[r];
    const float* wk = Wkp + r*64;
    const float* wv = Wvp + r*64;
    #pragma unroll 8
    for (int d = 0; d < 64; d++) {
        aK += kr[sub][d]*wk[d];
        aV += vr[sub][d]*wv[d];
    }
    g_Kp[pos*64 + r] = aK;
    g_Vp[pos*64 + r] = aV;
}

// ============================================== local window attention =====
__global__ void local_kernel() {
    int warp = threadIdx.x >> 5, lane = threadIdx.x & 31;
    int gq = blockIdx.x*8 + warp;         // (bh,s) flat
    int bh = gq >> 11, s = gq & 2047;
    const float* Qr = g_Q + gq*64;
    float q0 = Qr[lane], q1 = Qr[lane + 32];

    float sc[5];
    #pragma unroll
    for (int w = 0; w < 5; w++) {
        int j = s - 2 + w;
        float v = -INFINITY;
        if (j >= 0 && j < S) {
            const float* Kr = g_K + (bh*S + j)*64;
            float p = q0*Kr[lane] + q1*Kr[lane+32];
            #pragma unroll
            for (int o = 16; o > 0; o >>= 1) p += __shfl_xor_sync(0xffffffffu, p, o);
            v = p * 0.125f;
        }
        sc[w] = v;
    }
    float m = sc[0];
    #pragma unroll
    for (int w = 1; w < 5; w++) m = fmaxf(m, sc[w]);
    float e[5], ssum = 0.f;
    #pragma unroll
    for (int w = 0; w < 5; w++) { e[w] = expf(sc[w] - m); ssum += e[w]; }
    float inv = 1.f / ssum;
    float o0 = 0.f, o1 = 0.f;
    #pragma unroll
    for (int w = 0; w < 5; w++) {
        int j = s - 2 + w;
        if (j >= 0 && j < S) {
            const float* Vr = g_V + (bh*S + j)*64;
            float p = e[w]*inv;
            o0 += p*Vr[lane]; o1 += p*Vr[lane+32];
        }
    }
    int b = bh >> 3, hh = bh & 7;
    g_attn[(b*S + s)*HID + hh*64 + lane]      = o0;
    g_attn[(b*S + s)*HID + hh*64 + lane + 32] = o1;
}

// ============================================== global sparse attention ====
// per (b,h), per 64-query tile: scores vs all 2048 Kp, streamed top-16,
// softmax, Vp gather, Wvp projection, combine with local (0.5*(local+sp))
__global__ void global_kernel(const float* __restrict__ Wvp, const float* __restrict__ bvp) {
    __shared__ float Qs[64][65];          // Q tile; reused later as sp[64][r]
    __shared__ float Ks[32][65];
    __shared__ float Ss[64][33];
    __shared__ float tv[64][17];          // sorted desc top-16 values
    __shared__ int   ti[64][17];

    int bh = blockIdx.y;
    int q0 = blockIdx.x * 64;
    int tid = threadIdx.x;

    for (int e = tid; e < 64*64; e += 256) {
        int q = e >> 6, d = e & 63;
        Qs[q][d] = g_Q[(bh*S + q0 + q)*64 + d];
    }
    for (int e = tid; e < 64*16; e += 256) {
        tv[e >> 4][e & 15] = -INFINITY;
        ti[e >> 4][e & 15] = 0;
    }
    __syncthreads();

    int ty = tid >> 3;                    // 0..31 -> 2 queries each
    int tx = tid & 7;                     // 0..7  -> 4 keys each
    int qb = ty*2, kb = tx*4;

    for (int kt = 0; kt < 64; kt++) {
        int k0 = kt * 32;
        for (int e = tid; e < 32*64; e += 256) {
            int kk = e >> 6, d = e & 63;
            Ks[kk][d] = g_Kp[(bh*S + k0 + kk)*64 + d];
        }
        __syncthreads();

        float acc[2][4] = {};
        #pragma unroll 8
        for (int d = 0; d < 64; d++) {
            float a0 = Qs[qb][d], a1 = Qs[qb+1][d];
            float bb0 = Ks[kb][d], bb1 = Ks[kb+1][d], bb2 = Ks[kb+2][d], bb3 = Ks[kb+3][d];
            acc[0][0] += a0*bb0; acc[0][1] += a0*bb1; acc[0][2] += a0*bb2; acc[0][3] += a0*bb3;
            acc[1][0] += a1*bb0; acc[1][1] += a1*bb1; acc[1][2] += a1*bb2; acc[1][3] += a1*bb3;
        }
        #pragma unroll
        for (int i = 0; i < 2; i++)
            #pragma unroll
            for (int j = 0; j < 4; j++)
                Ss[qb+i][kb+j] = acc[i][j] * 0.125f;
        __syncthreads();

        if (tid < 64) {                   // per-query top-16 maintenance
            int q = tid;
            #pragma unroll 4
            for (int j = 0; j < 32; j++) {
                float sv = Ss[q][j];
                if (sv > tv[q][15]) {
                    int p = 15;
                    while (p > 0 && tv[q][p-1] < sv) {
                        tv[q][p] = tv[q][p-1];
                        ti[q][p] = ti[q][p-1];
                        p--;
                    }
                    tv[q][p] = sv;
                    ti[q][p] = k0 + j;
                }
            }
        }
        __syncthreads();
    }

    // softmax of top-16 values (sorted desc -> [0] is max); overwrite tv with weights
    if (tid < 64) {
        int q = tid;
        float m = tv[q][0];
        float sum = 0.f;
        #pragma unroll
        for (int k = 0; k < TK; k++) { float e = expf(tv[q][k] - m); tv[q][k] = e; sum += e; }
        float inv = 1.f / sum;
        #pragma unroll
        for (int k = 0; k < TK; k++) tv[q][k] *= inv;
    }
    __syncthreads();

    // sp[q][r] = sum_k tw[k] * Vp[ti[k]][r]   (store into Qs, now free)
    {
        int t4 = tid & 3, q = tid >> 2;
        float w[TK]; int ix[TK];
        #pragma unroll
        for (int k = 0; k < TK; k++) { w[k] = tv[q][k]; ix[k] = ti[q][k]; }
        const float* Vb = g_Vp + (size_t)bh*S*64;
        for (int r = t4; r < 64; r += 4) {
            float a = 0.f;
            #pragma unroll
            for (int k = 0; k < TK; k++) a += w[k]*Vb[ix[k]*64 + r];
            Qs[q][r] = a;
        }
    }
    __syncthreads();

    // sp2[d] = bvp[d] + sum_r sp[r]*Wvp[d][r]; combine with local
    {
        int t4 = tid & 3, q = tid >> 2;
        int b = bh >> 3, hh = bh & 7;
        int s = q0 + q;
        for (int d = t4; d < 64; d += 4) {
            float a = bvp[d];
            const float* wr = Wvp + d*64;
            #pragma unroll 8
            for (int r = 0; r < 64; r++) a += Qs[q][r]*wr[r];
            int idx = (b*S + s)*HID + hh*64 + d;
            g_attn[idx] = 0.5f*(g_attn[idx] + a);
        }
    }
}

// ============================================== output proj + residual =====
__global__ void outproj_kernel(const float* __restrict__ Wo, const float* __restrict__ bo) {
    __shared__ float As[16][64];
    __shared__ float Bsm[16][64];
    int m0 = blockIdx.x * 64;
    int n0 = blockIdx.y * 64;
    int tid = threadIdx.x;
    int tx = tid & 15, ty = tid >> 4;
    float acc[4][4] = {};

    for (int k0 = 0; k0 < 512; k0 += 16) {
        #pragma unroll
        for (int u = 0; u < 4; u++) {
            int e = tid + u*256;
            int row = e >> 4, col = e & 15;
            As[col][row]  = g_attn[(m0+row)*HID + k0 + col];
            Bsm[col][row] = Wo[(n0+row)*HID + k0 + col];
        }
        __syncthreads();
        #pragma unroll
        for (int kk = 0; kk < 16; kk++) {
            float a[4], bb[4];
            #pragma unroll
            for (int i = 0; i < 4; i++) a[i]  = As[kk][ty*4 + i];
            #pragma unroll
            for (int j = 0; j < 4; j++) bb[j] = Bsm[kk][tx*4 + j];
            #pragma unroll
            for (int i = 0; i < 4; i++)
                #pragma unroll
                for (int j = 0; j < 4; j++) acc[i][j] += a[i]*bb[j];
        }
        __syncthreads();
    }
    #pragma unroll
    for (int i = 0; i < 4; i++) {
        int m = m0 + ty*4 + i;
        #pragma unroll
        for (int j = 0; j < 4; j++) {
            int n = n0 + tx*4 + j;
            g_res[m*HID + n] = acc[i][j] + bo[n] + g_h[m*HID + n];
        }
    }
}

// ============================================== layernorm ==================
__global__ void ln_kernel(const float* __restrict__ g, const float* __restrict__ bta,
                          float* __restrict__ out) {
    int row = blockIdx.x, tid = threadIdx.x;
    const float* rr = g_res + row*HID;
    float v0 = rr[tid], v1 = rr[tid + 256];
    float s = v0 + v1, sq = v0*v0 + v1*v1;
    __shared__ float rs[8], rq[8];
    #pragma unroll
    for (int o = 16; o > 0; o >>= 1) {
        s  += __shfl_xor_sync(0xffffffffu, s, o);
        sq += __shfl_xor_sync(0xffffffffu, sq, o);
    }
    if ((tid & 31) == 0) { rs[tid >> 5] = s; rq[tid >> 5] = sq; }
    __syncthreads();
    float ts = 0.f, tq = 0.f;
    #pragma unroll
    for (int i = 0; i < 8; i++) { ts += rs[i]; tq += rq[i]; }
    float mu = ts * (1.f/512.f);
    float var = tq * (1.f/512.f) - mu*mu;
    float rstd = rsqrtf(var + 1e-5f);
    out[row*HID + tid]       = (v0 - mu)*rstd*g[tid]       + bta[tid];
    out[row*HID + tid + 256] = (v1 - mu)*rstd*g[tid + 256] + bta[tid + 256];
}

// ============================================== launch =====================
extern "C" void kernel_launch(void* const* d_in, const int* in_sizes, int n_in,
                              void* d_out, int out_size) {
    const float* x   = (const float*)d_in[0];
    const float* w1  = (const float*)d_in[1];
    const float* b1  = (const float*)d_in[2];
    const float* w2  = (const float*)d_in[3];
    const float* b2  = (const float*)d_in[4];
    const float* w3  = (const float*)d_in[5];
    const float* b3  = (const float*)d_in[6];
    const float* Wq  = (const float*)d_in[7];
    const float* bq  = (const float*)d_in[8];
    const float* Wk  = (const float*)d_in[9];
    const float* bk  = (const float*)d_in[10];
    const float* Wv  = (const float*)d_in[11];
    const float* bv  = (const float*)d_in[12];
    const float* Wkp = (const float*)d_in[13];
    const float* bkp = (const float*)d_in[14];
    const float* Wvp = (const float*)d_in[15];
    const float* bvp = (const float*)d_in[16];
    const float* Wo  = (const float*)d_in[17];
    const float* bo  = (const float*)d_in[18];
    const float* lng = (const float*)d_in[19];
    const float* lnb = (const float*)d_in[20];
    float* out = (float*)d_out;

    conv_kernel<<<BS/16, 512>>>(x, w1, b1, w2, b2, w3, b3);
    qkv_kernel<<<dim3(BS/64, 24), 256>>>(Wq, bq, Wk, bk, Wv, bv);
    kpvp_kernel<<<NQ/4, 256>>>(Wkp, bkp, Wvp, bvp);
    local_kernel<<<NQ/8, 256>>>();
    global_kernel<<<dim3(S/64, B*NH), 256>>>(Wvp, bvp);
    outproj_kernel<<<dim3(BS/64, 8), 256>>>(Wo, bo);
    ln_kernel<<<BS, 256>>>(lng, lnb, out);
}